// round 15
// baseline (speedup 1.0000x reference)
#include <cuda_runtime.h>
#include <math.h>

#define LSEQ   8192
#define NBATCH 1024
#define NT     512
#define NSTATE 64
#define PI_F 3.14159265358979323846f

#define ANG8K  (-7.66990393942820614e-4f)   // -2*pi/8192

__device__ float2 g_wm[16384];   // kprep only
__device__ float2 g_kh[4100];
__device__ float2 g_kf[8200];
__device__ float4 g_ab[8192];    // (conj(A), conj(B)) per bin, 1/8192 folded in

// ---------------- complex helpers ----------------
static __device__ __forceinline__ float2 cmul(float2 a, float2 b) {
    return make_float2(a.x*b.x - a.y*b.y, a.x*b.y + a.y*b.x);
}
static __device__ __forceinline__ float2 cadd(float2 a, float2 b){ return make_float2(a.x+b.x, a.y+b.y); }
static __device__ __forceinline__ float2 csub(float2 a, float2 b){ return make_float2(a.x-b.x, a.y-b.y); }
static __device__ __forceinline__ float2 cconj(float2 a){ return make_float2(a.x, -a.y); }
static __device__ __forceinline__ float2 cscale(float2 a, float s){ return make_float2(a.x*s, a.y*s); }

// One swizzle: kills the s=1 radix-16 stage's 16-way store conflict.
template<int SW>
static __device__ __forceinline__ int swz(int i) {
    if (SW == 1) return i ^ ((i >> 4) & 15);
    return i;
}

// ---------------- merged setup (ALL fp32) ----------------
__global__ void setup_kernel(const float* __restrict__ Bv, const float* __restrict__ Cv) {
    if (blockIdx.x > 4096) {
        int k = (blockIdx.x - 4097) * 64 + threadIdx.x;
        float s, c;
        sincospif((float)k / 8192.0f, &s, &c);
        g_wm[k] = make_float2(c, -s);
        return;
    }
    __shared__ float shg[5];
    __shared__ float wsum[2][8];
    int f = blockIdx.x;
    int n = threadIdx.x;
    if (n == 0) {
        float th = (2.0f * PI_F / 8192.0f) * (float)f;
        float s, c;
        sincosf(th, &s, &c);      // fp32: no exact zero at Nyquist -> no NaN
        float nr = 1.0f - c, ni = -s;
        float dr = 1.0f + c, di = s;
        float dd = dr*dr + di*di;
        shg[0] = 20.0f * (nr*dr + ni*di) / dd;
        shg[1] = 20.0f * (ni*dr - nr*di) / dd;
        shg[2] = dr; shg[3] = di; shg[4] = dd;
    }
    __syncthreads();
    float gr = shg[0], gi = shg[1];
    float er = gr + 0.5f;
    float ei = gi - PI_F * (float)n;
    float inv = 1.0f / (er*er + ei*ei);
    float ir =  er * inv, ii = -ei * inv;
    float b0 = Bv[n];
    float a0 = Cv[n];
    float p2 = (float)n + 0.5f;
    float p  = sqrtf(p2);
    float v00 = a0*b0, v01 = a0*p, v10 = p*b0, v11 = p2;
    float acc[8] = { v00*ir, v00*ii, v01*ir, v01*ii,
                     v10*ir, v10*ii, v11*ir, v11*ii };
    #pragma unroll
    for (int off = 16; off; off >>= 1) {
        #pragma unroll
        for (int t = 0; t < 8; t++)
            acc[t] += __shfl_down_sync(0xffffffffu, acc[t], off);
    }
    if ((n & 31) == 0) {
        #pragma unroll
        for (int t = 0; t < 8; t++) wsum[n >> 5][t] = acc[t];
    }
    __syncthreads();
    if (n == 0) {
        float k00r = wsum[0][0]+wsum[1][0], k00i = wsum[0][1]+wsum[1][1];
        float k01r = wsum[0][2]+wsum[1][2], k01i = wsum[0][3]+wsum[1][3];
        float k10r = wsum[0][4]+wsum[1][4], k10i = wsum[0][5]+wsum[1][5];
        float k11r = wsum[0][6]+wsum[1][6], k11i = wsum[0][7]+wsum[1][7];
        float ur = 1.0f + k11r, ui = k11i;
        float t1r = k01r*ur - k01i*ui, t1i = k01r*ui + k01i*ur;
        float t2r = t1r*k10r - t1i*k10i, t2i = t1r*k10i + t1i*k10r;
        float hr = k00r - t2r, hi = k00i - t2i;
        float dr = shg[2], di = shg[3], dd = shg[4];
        float c2r = 2.0f*dr/dd, c2i = -2.0f*di/dd;
        g_kh[f] = make_float2(c2r*hr - c2i*hi, c2r*hi + c2i*hr);
    }
}

// ---------------- DFT8 pieces ----------------
static __device__ __forceinline__ void dft8_tail(
    float2 E0, float2 E1, float2 E2, float2 E3,
    float2 O0, float2 O1, float2 O2, float2 O3, float2* X) {
    const float Cq = 0.70710678118654752440f;
    float2 t0 = O0;
    float2 t1 = make_float2(Cq*(O1.x + O1.y), Cq*(O1.y - O1.x));
    float2 t2 = make_float2(O2.y, -O2.x);
    float2 t3 = make_float2(Cq*(O3.y - O3.x), -Cq*(O3.x + O3.y));
    X[0] = cadd(E0, t0); X[4] = csub(E0, t0);
    X[1] = cadd(E1, t1); X[5] = csub(E1, t1);
    X[2] = cadd(E2, t2); X[6] = csub(E2, t2);
    X[3] = cadd(E3, t3); X[7] = csub(E3, t3);
}

static __device__ __forceinline__ void dft8v(
    float2 a0, float2 a1, float2 a2, float2 a3,
    float2 a4, float2 a5, float2 a6, float2 a7, float2* X) {
    float2 ea = cadd(a0, a4), em = csub(a0, a4);
    float2 eb = cadd(a2, a6), en = csub(a2, a6);
    float2 ej = make_float2(-en.y, en.x);
    float2 oa = cadd(a1, a5), om = csub(a1, a5);
    float2 ob = cadd(a3, a7), on = csub(a3, a7);
    float2 oj = make_float2(-on.y, on.x);
    dft8_tail(cadd(ea,eb), csub(em,ej), csub(ea,eb), cadd(em,ej),
              cadd(oa,ob), csub(om,oj), csub(oa,ob), cadd(om,oj), X);
}

// DFT8 of (a,b,c,d,0,0,0,0)
static __device__ __forceinline__ void dft8zhi(
    float2 a, float2 b, float2 c, float2 d, float2* X) {
    float2 jc = make_float2(-c.y, c.x);
    float2 jd = make_float2(-d.y, d.x);
    dft8_tail(cadd(a,c), csub(a,jc), csub(a,c), cadd(a,jc),
              cadd(b,d), csub(b,jd), csub(b,d), cadd(b,jd), X);
}

// ---------------- DFT16 combine + twiddled scatter ----------------
// E = DFT8(even t), O = DFT8(odd t). X[j] = E[j] + w16^j O[j]; X[j+8] = E[j] - w16^j O[j].
// Scatter: dst[o + m*s] = w8192^{ps*m} * X[m].
template<int SWD>
static __device__ __forceinline__ void dft16_scatter(
    const float2* E, const float2* O, float2* dst, int o, int s, int ps) {
    const float c1 = 0.92387953251128675613f;
    const float s1 = 0.38268343236508977173f;
    const float Cq = 0.70710678118654752440f;
    float2 t[8];
    t[0] = O[0];
    t[1] = cmul(make_float2(c1, -s1), O[1]);
    t[2] = make_float2(Cq*(O[2].x + O[2].y), Cq*(O[2].y - O[2].x));
    t[3] = cmul(make_float2(s1, -c1), O[3]);
    t[4] = make_float2(O[4].y, -O[4].x);
    t[5] = cmul(make_float2(-s1, -c1), O[5]);
    t[6] = make_float2(Cq*(O[6].y - O[6].x), -Cq*(O[6].x + O[6].y));
    t[7] = cmul(make_float2(-c1, -s1), O[7]);
    float sn, cs;
    __sincosf((float)ps * ANG8K, &sn, &cs);   // |angle| <= 0.392 rad
    float2 w1 = make_float2(cs, sn);
    float2 w2 = cmul(w1, w1);
    float2 w4 = cmul(w2, w2);
    float2 w8p = cmul(w4, w4);
    dst[swz<SWD>(o)]         = cadd(E[0], t[0]);
    dst[swz<SWD>(o + 8*s)]   = cmul(w8p, csub(E[0], t[0]));
    float2 wj = w1;
    #pragma unroll
    for (int j = 1; j < 8; j++) {
        dst[swz<SWD>(o + j*s)]       = cmul(wj, cadd(E[j], t[j]));
        dst[swz<SWD>(o + (j+8)*s)]   = cmul(cmul(w8p, wj), csub(E[j], t[j]));
        wj = cmul(wj, w1);
    }
}

// In-place radix-16 stage: read 16 -> sync -> butterfly+write -> sync.
template<int LS, int SWS, int SWD>
static __device__ __forceinline__ void stage16_ip(float2* Cb, int tid) {
    float2 r[16];
    #pragma unroll
    for (int m = 0; m < 16; m++)
        r[m] = Cb[swz<SWS>(tid + (m << 9))];
    __syncthreads();
    float2 E[8], O[8];
    dft8v(r[0], r[2], r[4], r[6], r[8], r[10], r[12], r[14], E);
    dft8v(r[1], r[3], r[5], r[7], r[9], r[11], r[13], r[15], O);
    int p = tid >> LS, q = tid & ((1 << LS) - 1);
    dft16_scatter<SWD>(E, O, Cb, q + (p << (LS + 4)), 1 << LS, p << LS);
    __syncthreads();
}

// First stage of FFT1: reads x directly from gmem (upper half zero), writes T1.
static __device__ __forceinline__ void stage0_gmem16(const float2* __restrict__ xr,
                                                     float2* Cb, int tid) {
    float2 v[8];
    #pragma unroll
    for (int m = 0; m < 8; m++)
        v[m] = xr[tid + (m << 9)];
    float2 E[8], O[8];
    dft8zhi(v[0], v[2], v[4], v[6], E);
    dft8zhi(v[1], v[3], v[5], v[7], O);
    dft16_scatter<1>(E, O, Cb, tid << 4, 1, tid);
    __syncthreads();
}

// pointwise: C_out = conj(A)*conj(Zm) + conj(B)*Zp   (scale folded into table)
static __device__ __forceinline__ float2 ab_apply(float4 ab, float2 Zm, float2 Zp) {
    float zx = Zm.x, zy = -Zm.y;
    return make_float2(ab.x*zx - ab.y*zy + ab.z*Zp.x - ab.w*Zp.y,
                       ab.x*zy + ab.y*zx + ab.z*Zp.y + ab.w*Zp.x);
}

// ---------------- kprep's FFT (table twiddles; validated, two-buffer) ----------------
template<int NTH, bool ZHI, bool SKIPHI>
static __device__ __forceinline__ void fft8192_r8(float2* A, float2* B, int tid) {
    float2* src = A;
    float2* dst = B;
    #pragma unroll
    for (int st = 0; st < 4; st++) {
        const int ls = 3 * st;
        const int s  = 1 << ls;
        #pragma unroll
        for (int it = 0; it < 1024 / NTH; it++) {
            int idx = tid + it * NTH;
            int p = idx >> ls;
            int q = idx & (s - 1);
            float2 x0 = src[idx];
            float2 x1 = src[idx + 1024];
            float2 x2 = src[idx + 2048];
            float2 x3 = src[idx + 3072];
            float2 x4, x5, x6, x7;
            if (ZHI && st == 0) {
                x4 = x5 = x6 = x7 = make_float2(0.f, 0.f);
            } else {
                x4 = src[idx + 4096];
                x5 = src[idx + 5120];
                x6 = src[idx + 6144];
                x7 = src[idx + 7168];
            }
            float2 X[8];
            dft8v(x0, x1, x2, x3, x4, x5, x6, x7, X);
            int tw = (p << (ls + 1));
            float2 w1 = g_wm[tw];
            float2 w2 = cmul(w1, w1);
            float2 w3 = cmul(w2, w1);
            float2 w4 = cmul(w2, w2);
            float2 w5 = cmul(w3, w2);
            float2 w6 = cmul(w3, w3);
            float2 w7 = cmul(w4, w3);
            int o = q + (p << (ls + 3));
            dst[o]         = X[0];
            dst[o + s]     = cmul(w1, X[1]);
            dst[o + 2*s]   = cmul(w2, X[2]);
            dst[o + 3*s]   = cmul(w3, X[3]);
            dst[o + 4*s]   = cmul(w4, X[4]);
            dst[o + 5*s]   = cmul(w5, X[5]);
            dst[o + 6*s]   = cmul(w6, X[6]);
            dst[o + 7*s]   = cmul(w7, X[7]);
        }
        __syncthreads();
        float2* t = src; src = dst; dst = t;
    }
    #pragma unroll
    for (int it = 0; it < 4096 / NTH; it++) {
        int q = tid + it * NTH;
        float2 a = src[q], b = src[q + 4096];
        dst[q] = cadd(a, b);
        if (!SKIPHI) dst[q + 4096] = csub(a, b);
    }
    __syncthreads();
}

// ---------------- K preparation + AB table ----------------
__global__ void kprep_kernel() {
    extern __shared__ float2 sm[];
    float2* A = sm;
    float2* B = sm + 8192;
    int tid = threadIdx.x;

    #pragma unroll
    for (int it = 0; it < 16; it++) {
        int f = tid + it * NT;
        float2 kh = (f <= 4096) ? g_kh[f] : g_kh[8192 - f];
        A[f] = (f <= 4096) ? cconj(kh) : kh;
    }
    __syncthreads();
    fft8192_r8<NT, false, false>(A, B, tid);
    const float sc = 1.0f / 8192.0f;
    #pragma unroll
    for (int it = 0; it < 8; it++) {
        int j = tid + it * NT;
        A[j] = make_float2(B[2*j].x * sc, B[2*j + 1].x * sc);
    }
    __syncthreads();
    fft8192_r8<NT, true, false>(A, B, tid);
    for (int k = tid; k <= 4096; k += NT) {
        if (k == 0) {
            float2 Z0 = B[0];
            g_kf[0]    = make_float2(Z0.x + Z0.y, 0.f);
            g_kf[8192] = make_float2(Z0.x - Z0.y, 0.f);
        } else {
            int hk = 8192 - k;
            float2 Zk  = B[k];
            float2 Zhc = cconj(B[hk]);
            float2 E  = cscale(cadd(Zk, Zhc), 0.5f);
            float2 Om = csub(Zk, Zhc);
            float2 O  = make_float2(0.5f * Om.y, -0.5f * Om.x);
            float2 w  = g_wm[k];
            g_kf[k] = cadd(E, cmul(w, O));
            if (k != 4096) {
                float2 wh = make_float2(-w.x, w.y);
                g_kf[hk] = cadd(cconj(E), cmul(wh, cconj(O)));
            }
        }
    }
    __syncthreads();
    // AB table: Zy[k] = A*Z[k] + B*conj(Z[h]);  A = ((1+s)/2)Kf[k] + ((1-s)/2)conj(Kf[h]),
    // B = (ic/2)(Kf[k] - conj(Kf[h])), w = (c,s) = exp(-2*pi*i*k/16384). Store conj, scaled.
    const float sc2 = 1.0f / 8192.0f;
    for (int k = tid; k < 8192; k += NT) {
        int hh = 8192 - k;                 // 8192 when k==0 (Nyquist partner of DC)
        float2 w  = g_wm[k];
        float2 Kk = g_kf[k];
        float2 Kh = g_kf[hh];
        float2 Khc = make_float2(Kh.x, -Kh.y);
        float ap = 0.5f * (1.0f + w.y), am = 0.5f * (1.0f - w.y);
        float2 Av = make_float2(ap*Kk.x + am*Khc.x, ap*Kk.y + am*Khc.y);
        float2 dd = csub(Kk, Khc);
        float2 Bv = make_float2(-0.5f*w.x*dd.y, 0.5f*w.x*dd.x);
        g_ab[k] = make_float4(Av.x*sc2, -Av.y*sc2, Bv.x*sc2, -Bv.y*sc2);
    }
}

// ---------------- main conv: radix-16, in-place 64KB, 2 blocks/SM ----------------
__global__ void __launch_bounds__(NT, 2) conv_kernel(const float* __restrict__ x,
                                                     float* __restrict__ y) {
    extern __shared__ float2 C[];     // 8192 float2 = 64KB
    int b = blockIdx.x;
    int tid = threadIdx.x;

    const float2* xr = (const float2*)(x + (size_t)b * LSEQ);

    // FFT1: 3 radix-16 stages (radix-2 fused into pointwise)
    stage0_gmem16(xr, C, tid);        // gmem -> T1
    stage16_ip<4, 1, 0>(C, tid);      // T1 -> plain
    stage16_ip<8, 0, 0>(C, tid);      // plain -> plain (P, pre radix-2)

    // pointwise: quad-closed in-place, AB-linearized
    #pragma unroll
    for (int it = 0; it < 4; it++) {
        int k = tid + it * NT;        // 0..2047
        if (k == 0) {
            float2 Pa = C[0], Pb = C[4096];
            float2 Z0 = cadd(Pa, Pb), Z4 = csub(Pa, Pb);
            C[0]    = ab_apply(g_ab[0],    Z0, Z0);
            C[4096] = ab_apply(g_ab[4096], Z4, Z4);
            float2 Qa = C[2048], Qb = C[6144];
            float2 Za = cadd(Qa, Qb), Zb = csub(Qa, Qb);
            C[2048] = ab_apply(g_ab[2048], Za, Zb);
            C[6144] = ab_apply(g_ab[6144], Zb, Za);
        } else {
            int k3 = 4096 + k, k2 = 4096 - k, hk = 8192 - k;
            float2 Pa = C[k], Pb = C[k3], Pc = C[k2], Pd = C[hk];
            float2 Zk  = cadd(Pa, Pb), Zh  = csub(Pc, Pd);
            float2 Zk2 = cadd(Pc, Pd), Zh2 = csub(Pa, Pb);
            C[k]  = ab_apply(g_ab[k],  Zk,  Zh);
            C[hk] = ab_apply(g_ab[hk], Zh,  Zk);
            C[k2] = ab_apply(g_ab[k2], Zk2, Zh2);
            C[k3] = ab_apply(g_ab[k3], Zh2, Zk2);
        }
    }
    __syncthreads();

    // IFFT (conj trick): 3 radix-16 stages (radix-2 fused into output)
    stage16_ip<0, 0, 1>(C, tid);      // plain -> T1
    stage16_ip<4, 1, 0>(C, tid);      // T1 -> plain
    stage16_ip<8, 0, 0>(C, tid);      // plain -> plain (pre radix-2)

    // output: fused radix-2 (low half) + conj (scale already folded into AB)
    float2* yr = (float2*)(y + (size_t)b * LSEQ);
    #pragma unroll
    for (int it = 0; it < 8; it++) {
        int j = tid + it * NT;
        float2 f = cadd(C[j], C[j + 4096]);
        yr[j] = make_float2(f.x, -f.y);
    }
}

// ---------------- launch ----------------
extern "C" void kernel_launch(void* const* d_in, const int* in_sizes, int n_in,
                              void* d_out, int out_size) {
    const float* x  = (const float*)d_in[0];
    const float* Bv = (const float*)d_in[1];
    const float* Cv = (const float*)d_in[2];
    float* y = (float*)d_out;
    (void)in_sizes; (void)n_in; (void)out_size;

    const int smem_kprep = 2 * 8192 * (int)sizeof(float2);   // 131072 B
    const int smem_conv  = 8192 * (int)sizeof(float2);       // 65536 B
    cudaFuncSetAttribute(kprep_kernel, cudaFuncAttributeMaxDynamicSharedMemorySize, smem_kprep);
    cudaFuncSetAttribute(conv_kernel,  cudaFuncAttributeMaxDynamicSharedMemorySize, smem_conv);

    setup_kernel<<<4353, 64>>>(Bv, Cv);
    kprep_kernel<<<1, NT, smem_kprep>>>();
    conv_kernel<<<NBATCH, NT, smem_conv>>>(x, y);
}

// round 16
// speedup vs baseline: 1.5056x; 1.5056x over previous
#include <cuda_runtime.h>
#include <math.h>

#define LSEQ   8192
#define NBATCH 1024
#define NT     512
#define NSTATE 64
#define PI_F 3.14159265358979323846f

#define ANG8K  (-7.66990393942820614e-4f)   // -2*pi/8192

__device__ float2 g_wm[16384];   // kprep only
__device__ float2 g_kh[4100];
__device__ float2 g_kf[8200];
__device__ float4 g_ab[8192];    // (conj(A), conj(B)) per bin, 1/8192 folded in

// ---------------- complex helpers ----------------
static __device__ __forceinline__ float2 cmul(float2 a, float2 b) {
    return make_float2(a.x*b.x - a.y*b.y, a.x*b.y + a.y*b.x);
}
static __device__ __forceinline__ float2 cadd(float2 a, float2 b){ return make_float2(a.x+b.x, a.y+b.y); }
static __device__ __forceinline__ float2 csub(float2 a, float2 b){ return make_float2(a.x-b.x, a.y-b.y); }
static __device__ __forceinline__ float2 cconj(float2 a){ return make_float2(a.x, -a.y); }
static __device__ __forceinline__ float2 cscale(float2 a, float s){ return make_float2(a.x*s, a.y*s); }

// Per-pass smem swizzles (validated R11/R12): T1 kills s=1 8-way store conflict,
// T2 kills s=8 2-way store conflict; linear reads stay conflict-free.
template<int SW>
static __device__ __forceinline__ int swz(int i) {
    if (SW == 1) return i ^ ((i >> 3) & 15);
    if (SW == 2) return i ^ (((i >> 6) & 7) << 3);
    return i;
}

// ---------------- merged setup (ALL fp32) ----------------
__global__ void setup_kernel(const float* __restrict__ Bv, const float* __restrict__ Cv) {
    if (blockIdx.x > 4096) {
        int k = (blockIdx.x - 4097) * 64 + threadIdx.x;
        float s, c;
        sincospif((float)k / 8192.0f, &s, &c);
        g_wm[k] = make_float2(c, -s);
        return;
    }
    __shared__ float shg[5];
    __shared__ float wsum[2][8];
    int f = blockIdx.x;
    int n = threadIdx.x;
    if (n == 0) {
        float th = (2.0f * PI_F / 8192.0f) * (float)f;
        float s, c;
        sincosf(th, &s, &c);      // fp32: no exact zero at Nyquist -> no NaN
        float nr = 1.0f - c, ni = -s;
        float dr = 1.0f + c, di = s;
        float dd = dr*dr + di*di;
        shg[0] = 20.0f * (nr*dr + ni*di) / dd;
        shg[1] = 20.0f * (ni*dr - nr*di) / dd;
        shg[2] = dr; shg[3] = di; shg[4] = dd;
    }
    __syncthreads();
    float gr = shg[0], gi = shg[1];
    float er = gr + 0.5f;
    float ei = gi - PI_F * (float)n;
    float inv = 1.0f / (er*er + ei*ei);
    float ir =  er * inv, ii = -ei * inv;
    float b0 = Bv[n];
    float a0 = Cv[n];
    float p2 = (float)n + 0.5f;
    float p  = sqrtf(p2);
    float v00 = a0*b0, v01 = a0*p, v10 = p*b0, v11 = p2;
    float acc[8] = { v00*ir, v00*ii, v01*ir, v01*ii,
                     v10*ir, v10*ii, v11*ir, v11*ii };
    #pragma unroll
    for (int off = 16; off; off >>= 1) {
        #pragma unroll
        for (int t = 0; t < 8; t++)
            acc[t] += __shfl_down_sync(0xffffffffu, acc[t], off);
    }
    if ((n & 31) == 0) {
        #pragma unroll
        for (int t = 0; t < 8; t++) wsum[n >> 5][t] = acc[t];
    }
    __syncthreads();
    if (n == 0) {
        float k00r = wsum[0][0]+wsum[1][0], k00i = wsum[0][1]+wsum[1][1];
        float k01r = wsum[0][2]+wsum[1][2], k01i = wsum[0][3]+wsum[1][3];
        float k10r = wsum[0][4]+wsum[1][4], k10i = wsum[0][5]+wsum[1][5];
        float k11r = wsum[0][6]+wsum[1][6], k11i = wsum[0][7]+wsum[1][7];
        float ur = 1.0f + k11r, ui = k11i;
        float t1r = k01r*ur - k01i*ui, t1i = k01r*ui + k01i*ur;
        float t2r = t1r*k10r - t1i*k10i, t2i = t1r*k10i + t1i*k10r;
        float hr = k00r - t2r, hi = k00i - t2i;
        float dr = shg[2], di = shg[3], dd = shg[4];
        float c2r = 2.0f*dr/dd, c2i = -2.0f*di/dd;
        g_kh[f] = make_float2(c2r*hr - c2i*hi, c2r*hi + c2i*hr);
    }
}

// ---------------- DFT8 butterfly + twiddled scatter (R12-validated) ----------------
template<int SWD>
static __device__ __forceinline__ void dft8_store(
    float2 x0, float2 x1, float2 x2, float2 x3,
    float2 x4, float2 x5, float2 x6, float2 x7,
    float2* dst, int o, int s, int ps) {
    float2 ea = cadd(x0, x4), em = csub(x0, x4);
    float2 eb = cadd(x2, x6), en = csub(x2, x6);
    float2 ej = make_float2(-en.y, en.x);
    float2 E0 = cadd(ea, eb), E1 = csub(em, ej);
    float2 E2 = csub(ea, eb), E3 = cadd(em, ej);
    float2 oa = cadd(x1, x5), om = csub(x1, x5);
    float2 ob = cadd(x3, x7), on = csub(x3, x7);
    float2 oj = make_float2(-on.y, on.x);
    float2 O0 = cadd(oa, ob), O1 = csub(om, oj);
    float2 O2 = csub(oa, ob), O3 = cadd(om, oj);
    const float C = 0.70710678118654752440f;
    float2 t0 = O0;
    float2 t1 = make_float2(C*(O1.x + O1.y), C*(O1.y - O1.x));
    float2 t2 = make_float2(O2.y, -O2.x);
    float2 t3 = make_float2(C*(O3.y - O3.x), -C*(O3.x + O3.y));
    float2 X0 = cadd(E0, t0), X4 = csub(E0, t0);
    float2 X1 = cadd(E1, t1), X5 = csub(E1, t1);
    float2 X2 = cadd(E2, t2), X6 = csub(E2, t2);
    float2 X3 = cadd(E3, t3), X7 = csub(E3, t3);
    float sn, cs;
    __sincosf((float)ps * ANG8K, &sn, &cs);
    float2 w1 = make_float2(cs, sn);
    float2 w2 = cmul(w1, w1);
    float2 w3 = cmul(w2, w1);
    float2 w4 = cmul(w2, w2);
    float2 w5 = cmul(w3, w2);
    float2 w6 = cmul(w3, w3);
    float2 w7 = cmul(w4, w3);
    dst[swz<SWD>(o)]       = X0;
    dst[swz<SWD>(o + s)]   = cmul(w1, X1);
    dst[swz<SWD>(o + 2*s)] = cmul(w2, X2);
    dst[swz<SWD>(o + 3*s)] = cmul(w3, X3);
    dst[swz<SWD>(o + 4*s)] = cmul(w4, X4);
    dst[swz<SWD>(o + 5*s)] = cmul(w5, X5);
    dst[swz<SWD>(o + 6*s)] = cmul(w6, X6);
    dst[swz<SWD>(o + 7*s)] = cmul(w7, X7);
}

// In-place staged radix-8 stage: read 16 -> sync -> butterfly+write -> sync.
template<int LS, int SWS, int SWD>
static __device__ __forceinline__ void stage8_ip(float2* C, int tid) {
    float2 r[16];
    #pragma unroll
    for (int it = 0; it < 2; it++) {
        int idx = tid + it * NT;
        #pragma unroll
        for (int m = 0; m < 8; m++)
            r[it*8 + m] = C[swz<SWS>(idx + (m << 10))];
    }
    __syncthreads();
    #pragma unroll
    for (int it = 0; it < 2; it++) {
        int idx = tid + it * NT;
        int p = idx >> LS, q = idx & ((1 << LS) - 1);
        dft8_store<SWD>(r[it*8],r[it*8+1],r[it*8+2],r[it*8+3],
                        r[it*8+4],r[it*8+5],r[it*8+6],r[it*8+7],
                        C, q + (p << (LS + 3)), 1 << LS, p << LS);
    }
    __syncthreads();
}

// Last radix-8 stage (s=512): read set == write set per thread -> no middle sync.
static __device__ __forceinline__ void stage8_last_ip(float2* C, int q) {
    float2 r[16];
    #pragma unroll
    for (int t = 0; t < 16; t++) r[t] = C[q + (t << 9)];
    #pragma unroll
    for (int p = 0; p < 2; p++) {
        dft8_store<0>(r[p], r[2+p], r[4+p], r[6+p],
                      r[8+p], r[10+p], r[12+p], r[14+p],
                      C, q + (p << 12), 512, p << 9);
    }
    __syncthreads();
}

// stage 0 from gmem (upper half zero), writes T1. Trailing sync.
static __device__ __forceinline__ void stage0_gmem(const float2* __restrict__ xr,
                                                   float2* __restrict__ dst, int tid) {
    const float2 Z = make_float2(0.f, 0.f);
    #pragma unroll
    for (int it = 0; it < 2; it++) {
        int p = tid + it * NT;
        float2 x0 = xr[p];
        float2 x1 = xr[p + 1024];
        float2 x2 = xr[p + 2048];
        float2 x3 = xr[p + 3072];
        dft8_store<1>(x0,x1,x2,x3, Z,Z,Z,Z, dst, p << 3, 1, p);
    }
    __syncthreads();
}

// pointwise: returns sc*conj(Zy) = conj(A)*conj(Zm) + conj(B)*Zp (table pre-conj/scaled)
static __device__ __forceinline__ float2 ab_apply(float4 ab, float2 Zm, float2 Zp) {
    float zx = Zm.x, zy = -Zm.y;
    return make_float2(ab.x*zx - ab.y*zy + ab.z*Zp.x - ab.w*Zp.y,
                       ab.x*zy + ab.y*zx + ab.z*Zp.y + ab.w*Zp.x);
}

// ---------------- kprep's FFT (table twiddles; validated, two-buffer) ----------------
template<int NTH, bool ZHI, bool SKIPHI>
static __device__ __forceinline__ void fft8192_r8(float2* A, float2* B, int tid) {
    float2* src = A;
    float2* dst = B;
    #pragma unroll
    for (int st = 0; st < 4; st++) {
        const int ls = 3 * st;
        const int s  = 1 << ls;
        #pragma unroll
        for (int it = 0; it < 1024 / NTH; it++) {
            int idx = tid + it * NTH;
            int p = idx >> ls;
            int q = idx & (s - 1);
            float2 x0 = src[idx];
            float2 x1 = src[idx + 1024];
            float2 x2 = src[idx + 2048];
            float2 x3 = src[idx + 3072];
            float2 x4, x5, x6, x7;
            if (ZHI && st == 0) {
                x4 = x5 = x6 = x7 = make_float2(0.f, 0.f);
            } else {
                x4 = src[idx + 4096];
                x5 = src[idx + 5120];
                x6 = src[idx + 6144];
                x7 = src[idx + 7168];
            }
            float2 ea = cadd(x0, x4), em = csub(x0, x4);
            float2 eb = cadd(x2, x6), en = csub(x2, x6);
            float2 ej = make_float2(-en.y, en.x);
            float2 E0 = cadd(ea, eb), E1 = csub(em, ej);
            float2 E2 = csub(ea, eb), E3 = cadd(em, ej);
            float2 oa = cadd(x1, x5), om = csub(x1, x5);
            float2 ob = cadd(x3, x7), on = csub(x3, x7);
            float2 oj = make_float2(-on.y, on.x);
            float2 O0 = cadd(oa, ob), O1 = csub(om, oj);
            float2 O2 = csub(oa, ob), O3 = cadd(om, oj);
            const float C = 0.70710678118654752440f;
            float2 t0 = O0;
            float2 t1 = make_float2(C*(O1.x + O1.y), C*(O1.y - O1.x));
            float2 t2 = make_float2(O2.y, -O2.x);
            float2 t3 = make_float2(C*(O3.y - O3.x), -C*(O3.x + O3.y));
            float2 X0 = cadd(E0, t0), X4 = csub(E0, t0);
            float2 X1 = cadd(E1, t1), X5 = csub(E1, t1);
            float2 X2 = cadd(E2, t2), X6 = csub(E2, t2);
            float2 X3 = cadd(E3, t3), X7 = csub(E3, t3);
            int tw = (p << (ls + 1));
            float2 w1 = g_wm[tw];
            float2 w2 = cmul(w1, w1);
            float2 w3 = cmul(w2, w1);
            float2 w4 = cmul(w2, w2);
            float2 w5 = cmul(w3, w2);
            float2 w6 = cmul(w3, w3);
            float2 w7 = cmul(w4, w3);
            int o = q + (p << (ls + 3));
            dst[o]         = X0;
            dst[o + s]     = cmul(w1, X1);
            dst[o + 2*s]   = cmul(w2, X2);
            dst[o + 3*s]   = cmul(w3, X3);
            dst[o + 4*s]   = cmul(w4, X4);
            dst[o + 5*s]   = cmul(w5, X5);
            dst[o + 6*s]   = cmul(w6, X6);
            dst[o + 7*s]   = cmul(w7, X7);
        }
        __syncthreads();
        float2* t = src; src = dst; dst = t;
    }
    #pragma unroll
    for (int it = 0; it < 4096 / NTH; it++) {
        int q = tid + it * NTH;
        float2 a = src[q], b = src[q + 4096];
        dst[q] = cadd(a, b);
        if (!SKIPHI) dst[q + 4096] = csub(a, b);
    }
    __syncthreads();
}

// ---------------- K preparation + AB table (R15-validated) ----------------
__global__ void kprep_kernel() {
    extern __shared__ float2 sm[];
    float2* A = sm;
    float2* B = sm + 8192;
    int tid = threadIdx.x;

    #pragma unroll
    for (int it = 0; it < 16; it++) {
        int f = tid + it * NT;
        float2 kh = (f <= 4096) ? g_kh[f] : g_kh[8192 - f];
        A[f] = (f <= 4096) ? cconj(kh) : kh;
    }
    __syncthreads();
    fft8192_r8<NT, false, false>(A, B, tid);
    const float sc = 1.0f / 8192.0f;
    #pragma unroll
    for (int it = 0; it < 8; it++) {
        int j = tid + it * NT;
        A[j] = make_float2(B[2*j].x * sc, B[2*j + 1].x * sc);
    }
    __syncthreads();
    fft8192_r8<NT, true, false>(A, B, tid);
    for (int k = tid; k <= 4096; k += NT) {
        if (k == 0) {
            float2 Z0 = B[0];
            g_kf[0]    = make_float2(Z0.x + Z0.y, 0.f);
            g_kf[8192] = make_float2(Z0.x - Z0.y, 0.f);
        } else {
            int hk = 8192 - k;
            float2 Zk  = B[k];
            float2 Zhc = cconj(B[hk]);
            float2 E  = cscale(cadd(Zk, Zhc), 0.5f);
            float2 Om = csub(Zk, Zhc);
            float2 O  = make_float2(0.5f * Om.y, -0.5f * Om.x);
            float2 w  = g_wm[k];
            g_kf[k] = cadd(E, cmul(w, O));
            if (k != 4096) {
                float2 wh = make_float2(-w.x, w.y);
                g_kf[hk] = cadd(cconj(E), cmul(wh, cconj(O)));
            }
        }
    }
    __syncthreads();
    // AB table: Zy[k] = A*Z[k] + B*conj(Z[h]);  A = ((1+s)/2)Kf[k] + ((1-s)/2)conj(Kf[h]),
    // B = (ic/2)(Kf[k] - conj(Kf[h])), w = (c,s) = exp(-2*pi*i*k/16384). Store conj, scaled.
    const float sc2 = 1.0f / 8192.0f;
    for (int k = tid; k < 8192; k += NT) {
        int hh = 8192 - k;                 // 8192 when k==0
        float2 w  = g_wm[k];
        float2 Kk = g_kf[k];
        float2 Kh = g_kf[hh];
        float2 Khc = make_float2(Kh.x, -Kh.y);
        float ap = 0.5f * (1.0f + w.y), am = 0.5f * (1.0f - w.y);
        float2 Av = make_float2(ap*Kk.x + am*Khc.x, ap*Kk.y + am*Khc.y);
        float2 dd = csub(Kk, Khc);
        float2 Bv = make_float2(-0.5f*w.x*dd.y, 0.5f*w.x*dd.x);
        g_ab[k] = make_float4(Av.x*sc2, -Av.y*sc2, Bv.x*sc2, -Bv.y*sc2);
    }
}

// ---------------- main conv: radix-8 in-place 64KB, 2 blocks/SM, AB pointwise ----------------
__global__ void __launch_bounds__(NT, 2) conv_kernel(const float* __restrict__ x,
                                                     float* __restrict__ y) {
    extern __shared__ float2 C[];     // 8192 float2 = 64KB
    int b = blockIdx.x;
    int tid = threadIdx.x;

    const float2* xr = (const float2*)(x + (size_t)b * LSEQ);

    // FFT1
    stage0_gmem(xr, C, tid);          // -> T1
    stage8_ip<3, 1, 2>(C, tid);       // T1 -> T2
    stage8_ip<6, 2, 0>(C, tid);       // T2 -> plain
    stage8_last_ip(C, tid);           // plain -> plain (P, pre final radix-2)

    // pointwise: quad-closed in-place, AB-linearized (radix-2 fused)
    #pragma unroll
    for (int it = 0; it < 4; it++) {
        int k = tid + it * NT;        // 0..2047
        if (k == 0) {
            float2 Pa = C[0], Pb = C[4096];
            float2 Z0 = cadd(Pa, Pb), Z4 = csub(Pa, Pb);
            C[0]    = ab_apply(g_ab[0],    Z0, Z0);
            C[4096] = ab_apply(g_ab[4096], Z4, Z4);
            float2 Qa = C[2048], Qb = C[6144];
            float2 Za = cadd(Qa, Qb), Zb = csub(Qa, Qb);
            C[2048] = ab_apply(g_ab[2048], Za, Zb);
            C[6144] = ab_apply(g_ab[6144], Zb, Za);
        } else {
            int k3 = 4096 + k, k2 = 4096 - k, hk = 8192 - k;
            float2 Pa = C[k], Pb = C[k3], Pc = C[k2], Pd = C[hk];
            float2 Zk  = cadd(Pa, Pb), Zh  = csub(Pc, Pd);
            float2 Zk2 = cadd(Pc, Pd), Zh2 = csub(Pa, Pb);
            C[k]  = ab_apply(g_ab[k],  Zk,  Zh);
            C[hk] = ab_apply(g_ab[hk], Zh,  Zk);
            C[k2] = ab_apply(g_ab[k2], Zk2, Zh2);
            C[k3] = ab_apply(g_ab[k3], Zh2, Zk2);
        }
    }
    __syncthreads();

    // IFFT (conj trick; input conj(Zy) in C, plain)
    stage8_ip<0, 0, 1>(C, tid);       // plain -> T1
    stage8_ip<3, 1, 2>(C, tid);       // T1 -> T2
    stage8_ip<6, 2, 0>(C, tid);       // T2 -> plain
    stage8_last_ip(C, tid);           // plain -> plain (pre final radix-2)

    // output: fused final radix-2 (low half) + conj (scale folded into AB)
    float2* yr = (float2*)(y + (size_t)b * LSEQ);
    #pragma unroll
    for (int it = 0; it < 8; it++) {
        int j = tid + it * NT;
        float2 f = cadd(C[j], C[j + 4096]);
        yr[j] = make_float2(f.x, -f.y);
    }
}

// ---------------- launch ----------------
extern "C" void kernel_launch(void* const* d_in, const int* in_sizes, int n_in,
                              void* d_out, int out_size) {
    const float* x  = (const float*)d_in[0];
    const float* Bv = (const float*)d_in[1];
    const float* Cv = (const float*)d_in[2];
    float* y = (float*)d_out;
    (void)in_sizes; (void)n_in; (void)out_size;

    const int smem_kprep = 2 * 8192 * (int)sizeof(float2);   // 131072 B
    const int smem_conv  = 8192 * (int)sizeof(float2);       // 65536 B
    cudaFuncSetAttribute(kprep_kernel, cudaFuncAttributeMaxDynamicSharedMemorySize, smem_kprep);
    cudaFuncSetAttribute(conv_kernel,  cudaFuncAttributeMaxDynamicSharedMemorySize, smem_conv);

    setup_kernel<<<4353, 64>>>(Bv, Cv);
    kprep_kernel<<<1, NT, smem_kprep>>>();
    conv_kernel<<<NBATCH, NT, smem_conv>>>(x, y);
}

// round 17
// speedup vs baseline: 1.5551x; 1.0328x over previous
#include <cuda_runtime.h>
#include <math.h>

#define LSEQ   8192
#define NBATCH 1024
#define NT     512
#define NSTATE 64
#define PI_F 3.14159265358979323846f

#define ANG8K  (-7.66990393942820614e-4f)   // -2*pi/8192

#define W16C1  0.92387953251128675613f
#define W16S1  0.38268343236508977173f
#define RSQ2   0.70710678118654752440f

__device__ float2 g_wm[16384];   // kprep only
__device__ float2 g_kh[4100];
__device__ float2 g_kf[8200];
__device__ float4 g_ab[8192];    // (conj(A), conj(B)) per bin, 1/8192 folded in

// ---------------- complex helpers ----------------
static __device__ __forceinline__ float2 cmul(float2 a, float2 b) {
    return make_float2(a.x*b.x - a.y*b.y, a.x*b.y + a.y*b.x);
}
static __device__ __forceinline__ float2 cadd(float2 a, float2 b){ return make_float2(a.x+b.x, a.y+b.y); }
static __device__ __forceinline__ float2 csub(float2 a, float2 b){ return make_float2(a.x-b.x, a.y-b.y); }
static __device__ __forceinline__ float2 cconj(float2 a){ return make_float2(a.x, -a.y); }
static __device__ __forceinline__ float2 cscale(float2 a, float s){ return make_float2(a.x*s, a.y*s); }

// w16^j * v, constant rotations (j = 0..7)
static __device__ __forceinline__ float2 w16mul(int j, float2 v) {
    switch (j) {
        case 0: return v;
        case 1: return cmul(make_float2( W16C1, -W16S1), v);
        case 2: return make_float2(RSQ2*(v.x + v.y), RSQ2*(v.y - v.x));
        case 3: return cmul(make_float2( W16S1, -W16C1), v);
        case 4: return make_float2(v.y, -v.x);
        case 5: return cmul(make_float2(-W16S1, -W16C1), v);
        case 6: return make_float2(RSQ2*(v.y - v.x), -RSQ2*(v.x + v.y));
        default:return cmul(make_float2(-W16C1, -W16S1), v);
    }
}

// Per-pass smem swizzles (validated): T1 kills s=1 8-way store conflict,
// T2 kills s=8 2-way store conflict; linear reads stay conflict-free.
template<int SW>
static __device__ __forceinline__ int swz(int i) {
    if (SW == 1) return i ^ ((i >> 3) & 15);
    if (SW == 2) return i ^ (((i >> 6) & 7) << 3);
    return i;
}

// ---------------- merged setup (ALL fp32) ----------------
__global__ void setup_kernel(const float* __restrict__ Bv, const float* __restrict__ Cv) {
    if (blockIdx.x > 4096) {
        int k = (blockIdx.x - 4097) * 64 + threadIdx.x;
        float s, c;
        sincospif((float)k / 8192.0f, &s, &c);
        g_wm[k] = make_float2(c, -s);
        return;
    }
    __shared__ float shg[5];
    __shared__ float wsum[2][8];
    int f = blockIdx.x;
    int n = threadIdx.x;
    if (n == 0) {
        float th = (2.0f * PI_F / 8192.0f) * (float)f;
        float s, c;
        sincosf(th, &s, &c);      // fp32: no exact zero at Nyquist -> no NaN
        float nr = 1.0f - c, ni = -s;
        float dr = 1.0f + c, di = s;
        float dd = dr*dr + di*di;
        shg[0] = 20.0f * (nr*dr + ni*di) / dd;
        shg[1] = 20.0f * (ni*dr - nr*di) / dd;
        shg[2] = dr; shg[3] = di; shg[4] = dd;
    }
    __syncthreads();
    float gr = shg[0], gi = shg[1];
    float er = gr + 0.5f;
    float ei = gi - PI_F * (float)n;
    float inv = 1.0f / (er*er + ei*ei);
    float ir =  er * inv, ii = -ei * inv;
    float b0 = Bv[n];
    float a0 = Cv[n];
    float p2 = (float)n + 0.5f;
    float p  = sqrtf(p2);
    float v00 = a0*b0, v01 = a0*p, v10 = p*b0, v11 = p2;
    float acc[8] = { v00*ir, v00*ii, v01*ir, v01*ii,
                     v10*ir, v10*ii, v11*ir, v11*ii };
    #pragma unroll
    for (int off = 16; off; off >>= 1) {
        #pragma unroll
        for (int t = 0; t < 8; t++)
            acc[t] += __shfl_down_sync(0xffffffffu, acc[t], off);
    }
    if ((n & 31) == 0) {
        #pragma unroll
        for (int t = 0; t < 8; t++) wsum[n >> 5][t] = acc[t];
    }
    __syncthreads();
    if (n == 0) {
        float k00r = wsum[0][0]+wsum[1][0], k00i = wsum[0][1]+wsum[1][1];
        float k01r = wsum[0][2]+wsum[1][2], k01i = wsum[0][3]+wsum[1][3];
        float k10r = wsum[0][4]+wsum[1][4], k10i = wsum[0][5]+wsum[1][5];
        float k11r = wsum[0][6]+wsum[1][6], k11i = wsum[0][7]+wsum[1][7];
        float ur = 1.0f + k11r, ui = k11i;
        float t1r = k01r*ur - k01i*ui, t1i = k01r*ui + k01i*ur;
        float t2r = t1r*k10r - t1i*k10i, t2i = t1r*k10i + t1i*k10r;
        float hr = k00r - t2r, hi = k00i - t2i;
        float dr = shg[2], di = shg[3], dd = shg[4];
        float c2r = 2.0f*dr/dd, c2i = -2.0f*di/dd;
        g_kh[f] = make_float2(c2r*hr - c2i*hi, c2r*hi + c2i*hr);
    }
}

// ---------------- DFT8 butterflies ----------------
static __device__ __forceinline__ void dft8_tail(
    float2 E0, float2 E1, float2 E2, float2 E3,
    float2 O0, float2 O1, float2 O2, float2 O3, float2* X) {
    float2 t0 = O0;
    float2 t1 = make_float2(RSQ2*(O1.x + O1.y), RSQ2*(O1.y - O1.x));
    float2 t2 = make_float2(O2.y, -O2.x);
    float2 t3 = make_float2(RSQ2*(O3.y - O3.x), -RSQ2*(O3.x + O3.y));
    X[0] = cadd(E0, t0); X[4] = csub(E0, t0);
    X[1] = cadd(E1, t1); X[5] = csub(E1, t1);
    X[2] = cadd(E2, t2); X[6] = csub(E2, t2);
    X[3] = cadd(E3, t3); X[7] = csub(E3, t3);
}

static __device__ __forceinline__ void dft8v(
    float2 a0, float2 a1, float2 a2, float2 a3,
    float2 a4, float2 a5, float2 a6, float2 a7, float2* X) {
    float2 ea = cadd(a0, a4), em = csub(a0, a4);
    float2 eb = cadd(a2, a6), en = csub(a2, a6);
    float2 ej = make_float2(-en.y, en.x);
    float2 oa = cadd(a1, a5), om = csub(a1, a5);
    float2 ob = cadd(a3, a7), on = csub(a3, a7);
    float2 oj = make_float2(-on.y, on.x);
    dft8_tail(cadd(ea,eb), csub(em,ej), csub(ea,eb), cadd(em,ej),
              cadd(oa,ob), csub(om,oj), csub(oa,ob), cadd(om,oj), X);
}

// DFT8 of (a,b,c,d,0,0,0,0)
static __device__ __forceinline__ void dft8zhi(
    float2 a, float2 b, float2 c, float2 d, float2* X) {
    float2 jc = make_float2(-c.y, c.x);
    float2 jd = make_float2(-d.y, d.x);
    dft8_tail(cadd(a,c), csub(a,jc), csub(a,c), cadd(a,jc),
              cadd(b,d), csub(b,jd), csub(b,d), cadd(b,jd), X);
}

// ---------------- twiddled scatter (general stages) ----------------
template<int SWD>
static __device__ __forceinline__ void scatter8(
    const float2* X, float2* dst, int o, int s, int ps) {
    float sn, cs;
    __sincosf((float)ps * ANG8K, &sn, &cs);
    float2 w1 = make_float2(cs, sn);
    float2 w2 = cmul(w1, w1);
    float2 w3 = cmul(w2, w1);
    float2 w4 = cmul(w2, w2);
    float2 w5 = cmul(w3, w2);
    float2 w6 = cmul(w3, w3);
    float2 w7 = cmul(w4, w3);
    dst[swz<SWD>(o)]       = X[0];
    dst[swz<SWD>(o + s)]   = cmul(w1, X[1]);
    dst[swz<SWD>(o + 2*s)] = cmul(w2, X[2]);
    dst[swz<SWD>(o + 3*s)] = cmul(w3, X[3]);
    dst[swz<SWD>(o + 4*s)] = cmul(w4, X[4]);
    dst[swz<SWD>(o + 5*s)] = cmul(w5, X[5]);
    dst[swz<SWD>(o + 6*s)] = cmul(w6, X[6]);
    dst[swz<SWD>(o + 7*s)] = cmul(w7, X[7]);
}

// In-place staged radix-8 stage: read 16 -> sync -> butterfly+write -> sync.
template<int LS, int SWS, int SWD>
static __device__ __forceinline__ void stage8_ip(float2* C, int tid) {
    float2 r[16];
    #pragma unroll
    for (int it = 0; it < 2; it++) {
        int idx = tid + it * NT;
        #pragma unroll
        for (int m = 0; m < 8; m++)
            r[it*8 + m] = C[swz<SWS>(idx + (m << 10))];
    }
    __syncthreads();
    #pragma unroll
    for (int it = 0; it < 2; it++) {
        int idx = tid + it * NT;
        int p = idx >> LS, q = idx & ((1 << LS) - 1);
        float2 X[8];
        dft8v(r[it*8],r[it*8+1],r[it*8+2],r[it*8+3],
              r[it*8+4],r[it*8+5],r[it*8+6],r[it*8+7], X);
        scatter8<SWD>(X, C, q + (p << (LS + 3)), 1 << LS, p << LS);
    }
    __syncthreads();
}

// Last radix-8 stage (s=512), in-place, CONSTANT twiddles:
// p=0 -> identity, p=1 -> w16^j. Read set == write set -> no middle sync.
static __device__ __forceinline__ void stage8_last_ip(float2* C, int q) {
    float2 r[16];
    #pragma unroll
    for (int t = 0; t < 16; t++) r[t] = C[q + (t << 9)];
    float2 X0[8], X1[8];
    dft8v(r[0], r[2], r[4], r[6], r[8], r[10], r[12], r[14], X0);
    dft8v(r[1], r[3], r[5], r[7], r[9], r[11], r[13], r[15], X1);
    #pragma unroll
    for (int j = 0; j < 8; j++) C[q + (j << 9)] = X0[j];
    #pragma unroll
    for (int j = 0; j < 8; j++) C[q + 4096 + (j << 9)] = w16mul(j, X1[j]);
    __syncthreads();
}

// IFFT's last radix-8 + final radix-2 + output store, fully fused.
// f[j] = X0[j] + w16^j * X1[j];  y = conj(f) (scale folded into AB table).
static __device__ __forceinline__ void stage8_last_out(const float2* C,
                                                       float2* __restrict__ yr, int q) {
    float2 r[16];
    #pragma unroll
    for (int t = 0; t < 16; t++) r[t] = C[q + (t << 9)];
    float2 X0[8], X1[8];
    dft8v(r[0], r[2], r[4], r[6], r[8], r[10], r[12], r[14], X0);
    dft8v(r[1], r[3], r[5], r[7], r[9], r[11], r[13], r[15], X1);
    #pragma unroll
    for (int j = 0; j < 8; j++) {
        float2 f = cadd(X0[j], w16mul(j, X1[j]));
        yr[q + (j << 9)] = make_float2(f.x, -f.y);
    }
}

// stage 0 from gmem (upper half zero, half-butterfly), writes T1. Trailing sync.
static __device__ __forceinline__ void stage0_gmem(const float2* __restrict__ xr,
                                                   float2* __restrict__ dst, int tid) {
    #pragma unroll
    for (int it = 0; it < 2; it++) {
        int p = tid + it * NT;
        float2 X[8];
        dft8zhi(xr[p], xr[p + 1024], xr[p + 2048], xr[p + 3072], X);
        scatter8<1>(X, dst, p << 3, 1, p);
    }
    __syncthreads();
}

// pointwise: returns sc*conj(Zy) = conj(A)*conj(Zm) + conj(B)*Zp (table pre-conj/scaled)
static __device__ __forceinline__ float2 ab_apply(float4 ab, float2 Zm, float2 Zp) {
    float zx = Zm.x, zy = -Zm.y;
    return make_float2(ab.x*zx - ab.y*zy + ab.z*Zp.x - ab.w*Zp.y,
                       ab.x*zy + ab.y*zx + ab.z*Zp.y + ab.w*Zp.x);
}

// ---------------- kprep's FFT (table twiddles; validated, two-buffer) ----------------
template<int NTH, bool ZHI, bool SKIPHI>
static __device__ __forceinline__ void fft8192_r8(float2* A, float2* B, int tid) {
    float2* src = A;
    float2* dst = B;
    #pragma unroll
    for (int st = 0; st < 4; st++) {
        const int ls = 3 * st;
        const int s  = 1 << ls;
        #pragma unroll
        for (int it = 0; it < 1024 / NTH; it++) {
            int idx = tid + it * NTH;
            int p = idx >> ls;
            int q = idx & (s - 1);
            float2 x0 = src[idx];
            float2 x1 = src[idx + 1024];
            float2 x2 = src[idx + 2048];
            float2 x3 = src[idx + 3072];
            float2 x4, x5, x6, x7;
            if (ZHI && st == 0) {
                x4 = x5 = x6 = x7 = make_float2(0.f, 0.f);
            } else {
                x4 = src[idx + 4096];
                x5 = src[idx + 5120];
                x6 = src[idx + 6144];
                x7 = src[idx + 7168];
            }
            float2 X[8];
            dft8v(x0, x1, x2, x3, x4, x5, x6, x7, X);
            int tw = (p << (ls + 1));
            float2 w1 = g_wm[tw];
            float2 w2 = cmul(w1, w1);
            float2 w3 = cmul(w2, w1);
            float2 w4 = cmul(w2, w2);
            float2 w5 = cmul(w3, w2);
            float2 w6 = cmul(w3, w3);
            float2 w7 = cmul(w4, w3);
            int o = q + (p << (ls + 3));
            dst[o]         = X[0];
            dst[o + s]     = cmul(w1, X[1]);
            dst[o + 2*s]   = cmul(w2, X[2]);
            dst[o + 3*s]   = cmul(w3, X[3]);
            dst[o + 4*s]   = cmul(w4, X[4]);
            dst[o + 5*s]   = cmul(w5, X[5]);
            dst[o + 6*s]   = cmul(w6, X[6]);
            dst[o + 7*s]   = cmul(w7, X[7]);
        }
        __syncthreads();
        float2* t = src; src = dst; dst = t;
    }
    #pragma unroll
    for (int it = 0; it < 4096 / NTH; it++) {
        int q = tid + it * NTH;
        float2 a = src[q], b = src[q + 4096];
        dst[q] = cadd(a, b);
        if (!SKIPHI) dst[q + 4096] = csub(a, b);
    }
    __syncthreads();
}

// ---------------- K preparation + AB table (validated) ----------------
__global__ void kprep_kernel() {
    extern __shared__ float2 sm[];
    float2* A = sm;
    float2* B = sm + 8192;
    int tid = threadIdx.x;

    #pragma unroll
    for (int it = 0; it < 16; it++) {
        int f = tid + it * NT;
        float2 kh = (f <= 4096) ? g_kh[f] : g_kh[8192 - f];
        A[f] = (f <= 4096) ? cconj(kh) : kh;
    }
    __syncthreads();
    fft8192_r8<NT, false, false>(A, B, tid);
    const float sc = 1.0f / 8192.0f;
    #pragma unroll
    for (int it = 0; it < 8; it++) {
        int j = tid + it * NT;
        A[j] = make_float2(B[2*j].x * sc, B[2*j + 1].x * sc);
    }
    __syncthreads();
    fft8192_r8<NT, true, false>(A, B, tid);
    for (int k = tid; k <= 4096; k += NT) {
        if (k == 0) {
            float2 Z0 = B[0];
            g_kf[0]    = make_float2(Z0.x + Z0.y, 0.f);
            g_kf[8192] = make_float2(Z0.x - Z0.y, 0.f);
        } else {
            int hk = 8192 - k;
            float2 Zk  = B[k];
            float2 Zhc = cconj(B[hk]);
            float2 E  = cscale(cadd(Zk, Zhc), 0.5f);
            float2 Om = csub(Zk, Zhc);
            float2 O  = make_float2(0.5f * Om.y, -0.5f * Om.x);
            float2 w  = g_wm[k];
            g_kf[k] = cadd(E, cmul(w, O));
            if (k != 4096) {
                float2 wh = make_float2(-w.x, w.y);
                g_kf[hk] = cadd(cconj(E), cmul(wh, cconj(O)));
            }
        }
    }
    __syncthreads();
    // AB table: Zy[k] = A*Z[k] + B*conj(Z[h]);  A = ((1+s)/2)Kf[k] + ((1-s)/2)conj(Kf[h]),
    // B = (ic/2)(Kf[k] - conj(Kf[h])), w = (c,s) = exp(-2*pi*i*k/16384). Store conj, scaled.
    const float sc2 = 1.0f / 8192.0f;
    for (int k = tid; k < 8192; k += NT) {
        int hh = 8192 - k;                 // 8192 when k==0
        float2 w  = g_wm[k];
        float2 Kk = g_kf[k];
        float2 Kh = g_kf[hh];
        float2 Khc = make_float2(Kh.x, -Kh.y);
        float ap = 0.5f * (1.0f + w.y), am = 0.5f * (1.0f - w.y);
        float2 Av = make_float2(ap*Kk.x + am*Khc.x, ap*Kk.y + am*Khc.y);
        float2 dd = csub(Kk, Khc);
        float2 Bv = make_float2(-0.5f*w.x*dd.y, 0.5f*w.x*dd.x);
        g_ab[k] = make_float4(Av.x*sc2, -Av.y*sc2, Bv.x*sc2, -Bv.y*sc2);
    }
}

// ---------------- main conv: radix-8 in-place 64KB, 2 blocks/SM ----------------
__global__ void __launch_bounds__(NT, 2) conv_kernel(const float* __restrict__ x,
                                                     float* __restrict__ y) {
    extern __shared__ float2 C[];     // 8192 float2 = 64KB
    int b = blockIdx.x;
    int tid = threadIdx.x;

    const float2* xr = (const float2*)(x + (size_t)b * LSEQ);

    // FFT1
    stage0_gmem(xr, C, tid);          // -> T1 (half-butterfly, zero upper half)
    stage8_ip<3, 1, 2>(C, tid);       // T1 -> T2
    stage8_ip<6, 2, 0>(C, tid);       // T2 -> plain
    stage8_last_ip(C, tid);           // plain -> plain (const twiddles; P, pre radix-2)

    // pointwise: quad-closed in-place, AB-linearized (radix-2 fused)
    #pragma unroll
    for (int it = 0; it < 4; it++) {
        int k = tid + it * NT;        // 0..2047
        if (k == 0) {
            float2 Pa = C[0], Pb = C[4096];
            float2 Z0 = cadd(Pa, Pb), Z4 = csub(Pa, Pb);
            C[0]    = ab_apply(g_ab[0],    Z0, Z0);
            C[4096] = ab_apply(g_ab[4096], Z4, Z4);
            float2 Qa = C[2048], Qb = C[6144];
            float2 Za = cadd(Qa, Qb), Zb = csub(Qa, Qb);
            C[2048] = ab_apply(g_ab[2048], Za, Zb);
            C[6144] = ab_apply(g_ab[6144], Zb, Za);
        } else {
            int k3 = 4096 + k, k2 = 4096 - k, hk = 8192 - k;
            float2 Pa = C[k], Pb = C[k3], Pc = C[k2], Pd = C[hk];
            float2 Zk  = cadd(Pa, Pb), Zh  = csub(Pc, Pd);
            float2 Zk2 = cadd(Pc, Pd), Zh2 = csub(Pa, Pb);
            C[k]  = ab_apply(g_ab[k],  Zk,  Zh);
            C[hk] = ab_apply(g_ab[hk], Zh,  Zk);
            C[k2] = ab_apply(g_ab[k2], Zk2, Zh2);
            C[k3] = ab_apply(g_ab[k3], Zh2, Zk2);
        }
    }
    __syncthreads();

    // IFFT (conj trick; input conj(Zy) in C, plain)
    stage8_ip<0, 0, 1>(C, tid);       // plain -> T1
    stage8_ip<3, 1, 2>(C, tid);       // T1 -> T2
    stage8_ip<6, 2, 0>(C, tid);       // T2 -> plain

    // fused: last radix-8 + final radix-2 + conj + gmem store
    float2* yr = (float2*)(y + (size_t)b * LSEQ);
    stage8_last_out(C, yr, tid);
}

// ---------------- launch ----------------
extern "C" void kernel_launch(void* const* d_in, const int* in_sizes, int n_in,
                              void* d_out, int out_size) {
    const float* x  = (const float*)d_in[0];
    const float* Bv = (const float*)d_in[1];
    const float* Cv = (const float*)d_in[2];
    float* y = (float*)d_out;
    (void)in_sizes; (void)n_in; (void)out_size;

    const int smem_kprep = 2 * 8192 * (int)sizeof(float2);   // 131072 B
    const int smem_conv  = 8192 * (int)sizeof(float2);       // 65536 B
    cudaFuncSetAttribute(kprep_kernel, cudaFuncAttributeMaxDynamicSharedMemorySize, smem_kprep);
    cudaFuncSetAttribute(conv_kernel,  cudaFuncAttributeMaxDynamicSharedMemorySize, smem_conv);

    setup_kernel<<<4353, 64>>>(Bv, Cv);
    kprep_kernel<<<1, NT, smem_kprep>>>();
    conv_kernel<<<NBATCH, NT, smem_conv>>>(x, y);
}